// round 4
// baseline (speedup 1.0000x reference)
#include <cuda_runtime.h>
#include <mma.h>
#include <math.h>

using namespace nvcuda;

#define N_NODES 50000
#define N_PAD   50048              // padded rows for full-tile wmma stores
#define N_EDGES 500000
#define NF      128
#define NH      4
#define NEG_SLOPE 0.2f
#define BN_EPS 1e-5f
#define SCAN_B  1024
#define N_SCANB ((N_NODES + SCAN_B - 1) / SCAN_B)   // 49

// ---------------- scratch (device globals; no allocation allowed) ----------
__device__ float g_h  [N_NODES * NF];
__device__ float g_h1 [N_PAD * NF];     // GEMM output (padded)
__device__ float g_fs [N_PAD * NF];     // GEMM output (padded)
__device__ float g_h2a[N_NODES * NF];
__device__ float g_h2b[N_NODES * NF];
__device__ float g_el [N_NODES * NH];
__device__ float g_er [N_NODES * NH];
__device__ double g_sum[NF];
__device__ double g_sq [NF];
__device__ float g_zero[NF];            // stays zero
// CSR (2 relations)
__device__ int g_deg   [2][N_NODES];
__device__ int g_rowptr[2][N_NODES + 1];
__device__ int g_cursor[2][N_NODES];
__device__ int g_colsrc[2][N_EDGES];
__device__ int g_bsum  [2][N_SCANB];

// ---------------- small utility kernels ----------------
__global__ void zero_stats() {
    g_sum[threadIdx.x] = 0.0;
    g_sq[threadIdx.x]  = 0.0;
}

__global__ void zero_deg(int r) {
    int i = blockIdx.x * blockDim.x + threadIdx.x;
    if (i < N_NODES) g_deg[r][i] = 0;
}

// ---------------- CSR build ----------------
__global__ void hist_deg(const int* __restrict__ dst, int r) {
    int e = blockIdx.x * blockDim.x + threadIdx.x;
    if (e < N_EDGES) atomicAdd(&g_deg[r][dst[e]], 1);
}

__global__ __launch_bounds__(SCAN_B)
void scan_blocks(int r) {
    __shared__ int tmp[SCAN_B];
    int i = blockIdx.x * SCAN_B + threadIdx.x;
    int v = (i < N_NODES) ? g_deg[r][i] : 0;
    tmp[threadIdx.x] = v;
    __syncthreads();
    for (int off = 1; off < SCAN_B; off <<= 1) {
        int t = (threadIdx.x >= off) ? tmp[threadIdx.x - off] : 0;
        __syncthreads();
        tmp[threadIdx.x] += t;
        __syncthreads();
    }
    if (i < N_NODES) g_rowptr[r][i] = tmp[threadIdx.x] - v;   // exclusive
    if (threadIdx.x == SCAN_B - 1) g_bsum[r][blockIdx.x] = tmp[SCAN_B - 1];
}

__global__ void scan_bsum(int r) {
    __shared__ int s[64];
    int v = (threadIdx.x < N_SCANB) ? g_bsum[r][threadIdx.x] : 0;
    s[threadIdx.x] = v;
    __syncthreads();
    for (int off = 1; off < 64; off <<= 1) {
        int t = (threadIdx.x >= off) ? s[threadIdx.x - off] : 0;
        __syncthreads();
        s[threadIdx.x] += t;
        __syncthreads();
    }
    if (threadIdx.x < N_SCANB) g_bsum[r][threadIdx.x] = s[threadIdx.x] - v;  // exclusive
}

__global__ void scan_finish(int r) {
    int i = blockIdx.x * blockDim.x + threadIdx.x;
    if (i < N_NODES) {
        int v = g_rowptr[r][i] + g_bsum[r][i / SCAN_B];
        g_rowptr[r][i] = v;
        g_cursor[r][i] = v;
    }
    if (i == 0) g_rowptr[r][N_NODES] = N_EDGES;
}

__global__ void scatter_csr(const int* __restrict__ src, const int* __restrict__ dst, int r) {
    int e = blockIdx.x * blockDim.x + threadIdx.x;
    if (e >= N_EDGES) return;
    int p = atomicAdd(&g_cursor[r][dst[e]], 1);
    g_colsrc[r][p] = src[e];
}

// ---------------- tf32x3 tensor-core GEMM: C[padded] = A @ W ----------------
// BM=128, BN=128(full), 256 thr = 8 warps (2x4), warp tile 64x32, wmma m16n16k8.
#define APAD 20
#define WPAD 132

__device__ __forceinline__ float tf32r(float v) { return wmma::__float_to_tf32(v); }

__global__ __launch_bounds__(256, 2)
void gemm128tc(const float* __restrict__ A, const float* __restrict__ W,
               float* __restrict__ C) {
    __shared__ float As_hi[128][APAD];
    __shared__ float As_lo[128][APAD];
    __shared__ float Ws_hi[16][WPAD];
    __shared__ float Ws_lo[16][WPAD];

    const int tid = threadIdx.x;
    const int rb = blockIdx.x * 128;
    const int warp = tid >> 5;
    const int wm = warp & 1;      // 0..1  -> rows wm*64
    const int wn = warp >> 1;     // 0..3  -> cols wn*32

    wmma::fragment<wmma::accumulator, 16, 16, 8, float> acc[4][2];
#pragma unroll
    for (int i = 0; i < 4; i++)
#pragma unroll
        for (int j = 0; j < 2; j++) wmma::fill_fragment(acc[i][j], 0.f);

    for (int kc = 0; kc < 128; kc += 16) {
        // A tile: 128 rows x 16 k  (512 float4, 2 per thread), row-guarded
#pragma unroll
        for (int u = 0; u < 2; u++) {
            int idx = tid * 2 + u;            // 0..511
            int row = idx >> 2;
            int kq  = (idx & 3) * 4;
            int gr  = rb + row;
            float4 v = make_float4(0.f, 0.f, 0.f, 0.f);
            if (gr < N_NODES) v = *(const float4*)&A[(size_t)gr * NF + kc + kq];
            float h0 = tf32r(v.x), h1 = tf32r(v.y), h2 = tf32r(v.z), h3 = tf32r(v.w);
            As_hi[row][kq + 0] = h0; As_lo[row][kq + 0] = tf32r(v.x - h0);
            As_hi[row][kq + 1] = h1; As_lo[row][kq + 1] = tf32r(v.y - h1);
            As_hi[row][kq + 2] = h2; As_lo[row][kq + 2] = tf32r(v.z - h2);
            As_hi[row][kq + 3] = h3; As_lo[row][kq + 3] = tf32r(v.w - h3);
        }
        // W tile: 16 k x 128 cols (512 float4, 2 per thread)
#pragma unroll
        for (int u = 0; u < 2; u++) {
            int idx = tid * 2 + u;
            int wr = idx >> 5;
            int wc = (idx & 31) * 4;
            float4 v = *(const float4*)&W[(size_t)(kc + wr) * NF + wc];
            float h0 = tf32r(v.x), h1 = tf32r(v.y), h2 = tf32r(v.z), h3 = tf32r(v.w);
            Ws_hi[wr][wc + 0] = h0; Ws_lo[wr][wc + 0] = tf32r(v.x - h0);
            Ws_hi[wr][wc + 1] = h1; Ws_lo[wr][wc + 1] = tf32r(v.y - h1);
            Ws_hi[wr][wc + 2] = h2; Ws_lo[wr][wc + 2] = tf32r(v.z - h2);
            Ws_hi[wr][wc + 3] = h3; Ws_lo[wr][wc + 3] = tf32r(v.w - h3);
        }
        __syncthreads();

#pragma unroll
        for (int ks = 0; ks < 16; ks += 8) {
            wmma::fragment<wmma::matrix_b, 16, 16, 8, wmma::precision::tf32, wmma::row_major> bh[2], bl[2];
#pragma unroll
            for (int j = 0; j < 2; j++) {
                wmma::load_matrix_sync(bh[j], &Ws_hi[ks][wn * 32 + j * 16], WPAD);
                wmma::load_matrix_sync(bl[j], &Ws_lo[ks][wn * 32 + j * 16], WPAD);
            }
#pragma unroll
            for (int i = 0; i < 4; i++) {
                wmma::fragment<wmma::matrix_a, 16, 16, 8, wmma::precision::tf32, wmma::row_major> ah, alo;
                wmma::load_matrix_sync(ah,  &As_hi[wm * 64 + i * 16][ks], APAD);
                wmma::load_matrix_sync(alo, &As_lo[wm * 64 + i * 16][ks], APAD);
#pragma unroll
                for (int j = 0; j < 2; j++) {
                    wmma::mma_sync(acc[i][j], ah,  bh[j], acc[i][j]);
                    wmma::mma_sync(acc[i][j], ah,  bl[j], acc[i][j]);
                    wmma::mma_sync(acc[i][j], alo, bh[j], acc[i][j]);
                }
            }
        }
        __syncthreads();
    }

#pragma unroll
    for (int i = 0; i < 4; i++)
#pragma unroll
        for (int j = 0; j < 2; j++) {
            int row0 = rb + wm * 64 + i * 16;       // always < N_PAD (padded C)
            wmma::store_matrix_sync(&C[(size_t)row0 * NF + wn * 32 + j * 16],
                                    acc[i][j], NF, wmma::mem_row_major);
        }
}

// ---------------- el/er from fs (small L2-resident pass) ----------------
__global__ __launch_bounds__(256)
void attn_ab(const float* __restrict__ fs, const float* __restrict__ al,
             const float* __restrict__ ar, float* __restrict__ el,
             float* __restrict__ er) {
    __shared__ float4 sal[32], sar[32];
    if (threadIdx.x < 32) {
        sal[threadIdx.x] = ((const float4*)al)[threadIdx.x];
        sar[threadIdx.x] = ((const float4*)ar)[threadIdx.x];
    }
    __syncthreads();
    int gw = (blockIdx.x * blockDim.x + threadIdx.x) >> 5;
    int lane = threadIdx.x & 31;
    if (gw >= N_NODES) return;
    float4 f = *(const float4*)&fs[(size_t)gw * NF + lane * 4];
    float4 a = sal[lane], b = sar[lane];
    float p = fmaf(f.x, a.x, fmaf(f.y, a.y, fmaf(f.z, a.z, f.w * a.w)));
    float q = fmaf(f.x, b.x, fmaf(f.y, b.y, fmaf(f.z, b.z, f.w * b.w)));
    p += __shfl_down_sync(0xffffffffu, p, 4, 8);
    p += __shfl_down_sync(0xffffffffu, p, 2, 8);
    p += __shfl_down_sync(0xffffffffu, p, 1, 8);
    q += __shfl_down_sync(0xffffffffu, q, 4, 8);
    q += __shfl_down_sync(0xffffffffu, q, 2, 8);
    q += __shfl_down_sync(0xffffffffu, q, 1, 8);
    if ((lane & 7) == 0) {
        el[gw * NH + (lane >> 3)] = p;
        er[gw * NH + (lane >> 3)] = q;
    }
}

// ---------------- fused GAT aggregation: warp per dst node ----------------
__global__ __launch_bounds__(256)
void gat_agg(int r, const float* __restrict__ el, const float* __restrict__ er,
             const float* __restrict__ fs, float* __restrict__ h2) {
    int d = (blockIdx.x * blockDim.x + threadIdx.x) >> 5;
    int lane = threadIdx.x & 31;
    if (d >= N_NODES) return;
    const int beg = g_rowptr[r][d];
    const int end = g_rowptr[r][d + 1];
    const float4 erd = *(const float4*)&er[d * NH];

    // phase 1: per-head sum of exp
    float s0 = 0.f, s1 = 0.f, s2 = 0.f, s3 = 0.f;
    for (int e = beg + lane; e < end; e += 32) {
        int s = g_colsrc[r][e];
        float4 elv = *(const float4*)&el[s * NH];
        float e0 = elv.x + erd.x; e0 = e0 > 0.f ? e0 : NEG_SLOPE * e0;
        float e1 = elv.y + erd.y; e1 = e1 > 0.f ? e1 : NEG_SLOPE * e1;
        float e2 = elv.z + erd.z; e2 = e2 > 0.f ? e2 : NEG_SLOPE * e2;
        float e3 = elv.w + erd.w; e3 = e3 > 0.f ? e3 : NEG_SLOPE * e3;
        s0 += expf(e0); s1 += expf(e1); s2 += expf(e2); s3 += expf(e3);
    }
#pragma unroll
    for (int off = 16; off >= 1; off >>= 1) {
        s0 += __shfl_xor_sync(0xffffffffu, s0, off);
        s1 += __shfl_xor_sync(0xffffffffu, s1, off);
        s2 += __shfl_xor_sync(0xffffffffu, s2, off);
        s3 += __shfl_xor_sync(0xffffffffu, s3, off);
    }

    // phase 2: weighted accumulate; lane covers fs cols lane*4..lane*4+3
    const int h = lane >> 3;
    const float er_h = (h == 0) ? erd.x : (h == 1) ? erd.y : (h == 2) ? erd.z : erd.w;
    const float s_h  = (h == 0) ? s0    : (h == 1) ? s1    : (h == 2) ? s2    : s3;
    const float inv_s = (end > beg) ? (1.f / s_h) : 0.f;
    const int co = lane * 4;

    float4 acc = make_float4(0.f, 0.f, 0.f, 0.f);
    int e = beg;
    for (; e + 2 <= end; e += 2) {           // unroll x2 for MLP
        int sA = g_colsrc[r][e];
        int sB = g_colsrc[r][e + 1];
        float4 ea = *(const float4*)&el[sA * NH];
        float4 eb = *(const float4*)&el[sB * NH];
        float4 fa = *(const float4*)&fs[(size_t)sA * NF + co];
        float4 fb = *(const float4*)&fs[(size_t)sB * NF + co];
        float elA = (h == 0) ? ea.x : (h == 1) ? ea.y : (h == 2) ? ea.z : ea.w;
        float elB = (h == 0) ? eb.x : (h == 1) ? eb.y : (h == 2) ? eb.z : eb.w;
        float vA = elA + er_h; vA = vA > 0.f ? vA : NEG_SLOPE * vA;
        float vB = elB + er_h; vB = vB > 0.f ? vB : NEG_SLOPE * vB;
        float aA = expf(vA) * inv_s;
        float aB = expf(vB) * inv_s;
        acc.x = fmaf(aA, fa.x, acc.x); acc.y = fmaf(aA, fa.y, acc.y);
        acc.z = fmaf(aA, fa.z, acc.z); acc.w = fmaf(aA, fa.w, acc.w);
        acc.x = fmaf(aB, fb.x, acc.x); acc.y = fmaf(aB, fb.y, acc.y);
        acc.z = fmaf(aB, fb.z, acc.z); acc.w = fmaf(aB, fb.w, acc.w);
    }
    if (e < end) {
        int s = g_colsrc[r][e];
        float4 ea = *(const float4*)&el[s * NH];
        float4 fa = *(const float4*)&fs[(size_t)s * NF + co];
        float elA = (h == 0) ? ea.x : (h == 1) ? ea.y : (h == 2) ? ea.z : ea.w;
        float vA = elA + er_h; vA = vA > 0.f ? vA : NEG_SLOPE * vA;
        float aA = expf(vA) * inv_s;
        acc.x = fmaf(aA, fa.x, acc.x); acc.y = fmaf(aA, fa.y, acc.y);
        acc.z = fmaf(aA, fa.z, acc.z); acc.w = fmaf(aA, fa.w, acc.w);
    }
    *(float4*)&h2[(size_t)d * NF + co] = acc;
}

// ---------------- layer finalize + BN ----------------
#define RPB 128
__global__ void finalize_stats(const float* __restrict__ h1,
                               const float* __restrict__ h2a,
                               const float* __restrict__ h2b,
                               const float* __restrict__ cb0,
                               const float* __restrict__ cb1,
                               const float* __restrict__ sb,
                               float* __restrict__ t) {
    int col = threadIdx.x;
    float bias = cb0[col] + cb1[col];
    float sbias = sb[col];
    int r0 = blockIdx.x * RPB;
    double s = 0.0, s2 = 0.0;
    for (int r = 0; r < RPB; r++) {
        int row = r0 + r;
        if (row >= N_NODES) break;
        float v = h2a[(size_t)row * NF + col] + h2b[(size_t)row * NF + col] + bias;
        v = v > 0.f ? v : 0.f;
        v += h1[(size_t)row * NF + col] + sbias;
        t[(size_t)row * NF + col] = v;
        s += v;
        s2 += (double)v * (double)v;
    }
    atomicAdd(&g_sum[col], s);
    atomicAdd(&g_sq[col], s2);
}

__global__ void stats128(const float* __restrict__ x, const float* __restrict__ bias) {
    int col = threadIdx.x;
    float b = bias[col];
    int r0 = blockIdx.x * RPB;
    double s = 0.0, s2 = 0.0;
    for (int r = 0; r < RPB; r++) {
        int row = r0 + r;
        if (row >= N_NODES) break;
        float v = x[(size_t)row * NF + col] + b;
        s += v;
        s2 += (double)v * (double)v;
    }
    atomicAdd(&g_sum[col], s);
    atomicAdd(&g_sq[col], s2);
}

__global__ void normalize128(const float* __restrict__ x, const float* __restrict__ bias,
                             const float* __restrict__ g, const float* __restrict__ b,
                             float* __restrict__ y, int do_relu) {
    int col = threadIdx.x;
    double mu = g_sum[col] / (double)N_NODES;
    double var = g_sq[col] / (double)N_NODES - mu * mu;
    float sc = g[col] * rsqrtf((float)var + BN_EPS);
    float sh = b[col] - (float)mu * sc;
    float bi = bias[col];
    int r0 = blockIdx.x * RPB;
    for (int r = 0; r < RPB; r++) {
        int row = r0 + r;
        if (row >= N_NODES) break;
        float v = (x[(size_t)row * NF + col] + bi) * sc + sh;
        if (do_relu) v = v > 0.f ? v : 0.f;
        y[(size_t)row * NF + col] = v;
    }
}

// ---------------- final 128 -> 16 GEMM ----------------
__global__ __launch_bounds__(128)
void gemm_out(const float* __restrict__ x, const float* __restrict__ W2,
              const float* __restrict__ b2, float* __restrict__ out) {
    __shared__ float xs[8][NF];
    int tid = threadIdx.x;
    int r0 = blockIdx.x * 8;
#pragma unroll
    for (int i = 0; i < 8; i++) {
        int row = r0 + i;
        xs[i][tid] = (row < N_NODES) ? x[(size_t)row * NF + tid] : 0.f;
    }
    __syncthreads();
    int row = tid >> 4;
    int c = tid & 15;
    float acc = b2[c];
#pragma unroll 8
    for (int k = 0; k < NF; k++) acc = fmaf(xs[row][k], W2[k * 16 + c], acc);
    if (r0 + row < N_NODES) out[(size_t)(r0 + row) * 16 + c] = acc;
}

// ---------------- host ----------------
extern "C" void kernel_launch(void* const* d_in, const int* in_sizes, int n_in,
                              void* d_out, int out_size) {
    const float* feat     = (const float*)d_in[0];
    const float* fc_W     = (const float*)d_in[1];
    const float* attn_l   = (const float*)d_in[2];
    const float* attn_r   = (const float*)d_in[3];
    const float* conv_b   = (const float*)d_in[4];
    const float* skip_W   = (const float*)d_in[5];
    const float* skip_b   = (const float*)d_in[6];
    const float* norm_g   = (const float*)d_in[7];
    const float* norm_b   = (const float*)d_in[8];
    const float* clf_W1   = (const float*)d_in[9];
    const float* clf_b1   = (const float*)d_in[10];
    const float* clf_g    = (const float*)d_in[11];
    const float* clf_b    = (const float*)d_in[12];
    const float* clf_W2   = (const float*)d_in[13];
    const float* clf_b2   = (const float*)d_in[14];
    const int*   src      = (const int*)d_in[15];
    const int*   dst      = (const int*)d_in[16];
    float* out = (float*)d_out;

    float *h, *h1, *fs, *h2a, *h2b, *el, *er, *zeros;
    cudaGetSymbolAddress((void**)&h,    g_h);
    cudaGetSymbolAddress((void**)&h1,   g_h1);
    cudaGetSymbolAddress((void**)&fs,   g_fs);
    cudaGetSymbolAddress((void**)&h2a,  g_h2a);
    cudaGetSymbolAddress((void**)&h2b,  g_h2b);
    cudaGetSymbolAddress((void**)&el,   g_el);
    cudaGetSymbolAddress((void**)&er,   g_er);
    cudaGetSymbolAddress((void**)&zeros, g_zero);

    const int gemm_grid = (N_PAD + 127) / 128;             // 391
    const int node_grid = (N_NODES + 255) / 256;
    const int edge_grid = (N_EDGES + 255) / 256;
    const int agg_grid  = (N_NODES * 32 + 255) / 256;
    const int bn_grid   = (N_NODES + RPB - 1) / RPB;

    // ---- CSR build (once, reused by both layers) ----
    for (int r = 0; r < 2; r++) {
        const int* dr = dst + (size_t)r * N_EDGES;
        const int* sr = src + (size_t)r * N_EDGES;
        zero_deg<<<node_grid, 256>>>(r);
        hist_deg<<<edge_grid, 256>>>(dr, r);
        scan_blocks<<<N_SCANB, SCAN_B>>>(r);
        scan_bsum<<<1, 64>>>(r);
        scan_finish<<<node_grid, 256>>>(r);
        scatter_csr<<<edge_grid, 256>>>(sr, dr, r);
    }

    const float* hin = feat;
    for (int l = 0; l < 2; l++) {
        gemm128tc<<<gemm_grid, 256>>>(hin, skip_W + l * NF * NF, h1);
        for (int r = 0; r < 2; r++) {
            int lr = l * 2 + r;
            gemm128tc<<<gemm_grid, 256>>>(hin, fc_W + (size_t)lr * NF * NF, fs);
            attn_ab<<<agg_grid, 256>>>(fs, attn_l + lr * NF, attn_r + lr * NF, el, er);
            gat_agg<<<agg_grid, 256>>>(r, el, er, fs, r == 0 ? h2a : h2b);
        }
        zero_stats<<<1, 128>>>();
        finalize_stats<<<bn_grid, 128>>>(h1, h2a, h2b,
                                         conv_b + (l * 2 + 0) * NF,
                                         conv_b + (l * 2 + 1) * NF,
                                         skip_b + l * NF, fs);
        normalize128<<<bn_grid, 128>>>(fs, zeros, norm_g + l * NF, norm_b + l * NF, h, 0);
        hin = h;
    }

    // classifier
    gemm128tc<<<gemm_grid, 256>>>(h, clf_W1, h1);
    zero_stats<<<1, 128>>>();
    stats128<<<bn_grid, 128>>>(h1, clf_b1);
    normalize128<<<bn_grid, 128>>>(h1, clf_b1, clf_g, clf_b, fs, 1);
    gemm_out<<<(N_NODES + 7) / 8, 128>>>(fs, clf_W2, clf_b2, out);
}

// round 5
// speedup vs baseline: 1.2134x; 1.2134x over previous
#include <cuda_runtime.h>
#include <math.h>

#define N_NODES 50000
#define N_EDGES 500000
#define NF      128
#define NH      4
#define NEG_SLOPE 0.2f
#define BN_EPS 1e-5f
#define SCAN_B  1024
#define N_SCANB ((N_NODES + SCAN_B - 1) / SCAN_B)   // 49

// ---------------- scratch (device globals; no allocation allowed) ----------
__device__ float g_h  [N_NODES * NF];
__device__ float g_h1 [N_NODES * NF];
__device__ float g_fs [N_NODES * NF];
__device__ float g_h2a[N_NODES * NF];
__device__ float g_h2b[N_NODES * NF];
__device__ float g_el [N_NODES * NH];
__device__ float g_er [N_NODES * NH];
__device__ double g_sum[NF];
__device__ double g_sq [NF];
// CSR (2 relations)
__device__ int g_deg   [2][N_NODES];
__device__ int g_rowptr[2][N_NODES + 1];
__device__ int g_cursor[2][N_NODES];
__device__ int g_colsrc[2][N_EDGES];
__device__ int g_bsum  [2][N_SCANB];

// ---------------- small utility kernels ----------------
__global__ void zero_stats() {
    g_sum[threadIdx.x] = 0.0;
    g_sq[threadIdx.x]  = 0.0;
}

__global__ void zero_deg(int r) {
    int i = blockIdx.x * blockDim.x + threadIdx.x;
    if (i < N_NODES) g_deg[r][i] = 0;
}

// ---------------- CSR build ----------------
__global__ void hist_deg(const int* __restrict__ dst, int r) {
    int e = blockIdx.x * blockDim.x + threadIdx.x;
    if (e < N_EDGES) atomicAdd(&g_deg[r][dst[e]], 1);
}

__global__ __launch_bounds__(SCAN_B)
void scan_blocks(int r) {
    __shared__ int tmp[SCAN_B];
    int i = blockIdx.x * SCAN_B + threadIdx.x;
    int v = (i < N_NODES) ? g_deg[r][i] : 0;
    tmp[threadIdx.x] = v;
    __syncthreads();
    for (int off = 1; off < SCAN_B; off <<= 1) {
        int t = (threadIdx.x >= off) ? tmp[threadIdx.x - off] : 0;
        __syncthreads();
        tmp[threadIdx.x] += t;
        __syncthreads();
    }
    if (i < N_NODES) g_rowptr[r][i] = tmp[threadIdx.x] - v;   // exclusive
    if (threadIdx.x == SCAN_B - 1) g_bsum[r][blockIdx.x] = tmp[SCAN_B - 1];
}

__global__ void scan_bsum(int r) {
    __shared__ int s[64];
    int v = (threadIdx.x < N_SCANB) ? g_bsum[r][threadIdx.x] : 0;
    s[threadIdx.x] = v;
    __syncthreads();
    for (int off = 1; off < 64; off <<= 1) {
        int t = (threadIdx.x >= off) ? s[threadIdx.x - off] : 0;
        __syncthreads();
        s[threadIdx.x] += t;
        __syncthreads();
    }
    if (threadIdx.x < N_SCANB) g_bsum[r][threadIdx.x] = s[threadIdx.x] - v;  // exclusive
}

__global__ void scan_finish(int r) {
    int i = blockIdx.x * blockDim.x + threadIdx.x;
    if (i < N_NODES) {
        int v = g_rowptr[r][i] + g_bsum[r][i / SCAN_B];
        g_rowptr[r][i] = v;
        g_cursor[r][i] = v;
    }
    if (i == 0) g_rowptr[r][N_NODES] = N_EDGES;
}

__global__ void scatter_csr(const int* __restrict__ src, const int* __restrict__ dst, int r) {
    int e = blockIdx.x * blockDim.x + threadIdx.x;
    if (e >= N_EDGES) return;
    int p = atomicAdd(&g_cursor[r][dst[e]], 1);
    g_colsrc[r][p] = src[e];
}

// ---------------- software-pipelined SGEMM (+ optional attn epilogue) ------
// BM=128, BN=128, BK=8, 256 threads, 8x8 microtile.
// W tiles: cp.async double buffer. A tiles: register-staged double buffer.
__device__ __forceinline__ void cp_async16(void* smem, const void* gmem) {
    unsigned sa = (unsigned)__cvta_generic_to_shared(smem);
    asm volatile("cp.async.cg.shared.global [%0], [%1], 16;\n"
                 :: "r"(sa), "l"(gmem));
}
__device__ __forceinline__ void cp_commit() {
    asm volatile("cp.async.commit_group;\n");
}
__device__ __forceinline__ void cp_wait0() {
    asm volatile("cp.async.wait_group 0;\n" ::: "memory");
}

__global__ __launch_bounds__(256, 2)
void gemm128(const float* __restrict__ A, const float* __restrict__ W,
             const float* __restrict__ bias, float* __restrict__ C,
             const float* __restrict__ al, const float* __restrict__ ar,
             float* __restrict__ elo, float* __restrict__ ero) {
    __shared__ float As[2][8][128];
    __shared__ float Ws[2][8][128];

    const int tid = threadIdx.x;
    const int tx = tid & 15;
    const int ty = tid >> 4;
    const int rb = blockIdx.x * 128;

    const int arow = tid >> 1;
    const int acol = (tid & 1) * 4;
    const int wrow = tid >> 5;
    const int wcol = (tid & 31) * 4;
    const int gr = rb + arow;
    const bool arow_ok = (gr < N_NODES);

    float acc[8][8];
#pragma unroll
    for (int i = 0; i < 8; i++)
#pragma unroll
        for (int j = 0; j < 8; j++) acc[i][j] = 0.f;

    // prologue: tile 0
    float4 av = make_float4(0.f, 0.f, 0.f, 0.f);
    if (arow_ok) av = *(const float4*)&A[(size_t)gr * NF + acol];
    cp_async16(&Ws[0][wrow][wcol], &W[(size_t)wrow * NF + wcol]);
    cp_commit();
    As[0][acol + 0][arow] = av.x;
    As[0][acol + 1][arow] = av.y;
    As[0][acol + 2][arow] = av.z;
    As[0][acol + 3][arow] = av.w;
    cp_wait0();
    __syncthreads();

    int buf = 0;
    for (int t = 0; t < 16; t++) {
        const int kc = t * 8;
        const bool has_next = (t + 1 < 16);
        float4 avn;
        if (has_next) {
            avn = make_float4(0.f, 0.f, 0.f, 0.f);
            if (arow_ok) avn = *(const float4*)&A[(size_t)gr * NF + kc + 8 + acol];
            cp_async16(&Ws[buf ^ 1][wrow][wcol], &W[(size_t)(kc + 8 + wrow) * NF + wcol]);
            cp_commit();
        }

#pragma unroll
        for (int kk = 0; kk < 8; kk++) {
            float a[8], b[8];
            *(float4*)&a[0] = *(float4*)&As[buf][kk][ty * 8];
            *(float4*)&a[4] = *(float4*)&As[buf][kk][ty * 8 + 4];
            *(float4*)&b[0] = *(float4*)&Ws[buf][kk][tx * 8];
            *(float4*)&b[4] = *(float4*)&Ws[buf][kk][tx * 8 + 4];
#pragma unroll
            for (int i = 0; i < 8; i++)
#pragma unroll
                for (int j = 0; j < 8; j++)
                    acc[i][j] = fmaf(a[i], b[j], acc[i][j]);
        }

        if (has_next) {
            As[buf ^ 1][acol + 0][arow] = avn.x;
            As[buf ^ 1][acol + 1][arow] = avn.y;
            As[buf ^ 1][acol + 2][arow] = avn.z;
            As[buf ^ 1][acol + 3][arow] = avn.w;
            cp_wait0();
        }
        __syncthreads();
        buf ^= 1;
    }

    const int cb = tx * 8;
    float bcol[8];
#pragma unroll
    for (int j = 0; j < 8; j++) bcol[j] = bias ? bias[cb + j] : 0.f;
    float alv[8], arv[8];
    if (elo) {
#pragma unroll
        for (int j = 0; j < 8; j++) { alv[j] = al[cb + j]; arv[j] = ar[cb + j]; }
    }
    const int hh = tx >> 2;

#pragma unroll
    for (int i = 0; i < 8; i++) {
        int row = rb + ty * 8 + i;
        if (row < N_NODES) {
            float4 o0 = make_float4(acc[i][0] + bcol[0], acc[i][1] + bcol[1],
                                    acc[i][2] + bcol[2], acc[i][3] + bcol[3]);
            float4 o1 = make_float4(acc[i][4] + bcol[4], acc[i][5] + bcol[5],
                                    acc[i][6] + bcol[6], acc[i][7] + bcol[7]);
            *(float4*)&C[(size_t)row * NF + cb]     = o0;
            *(float4*)&C[(size_t)row * NF + cb + 4] = o1;
        }
        if (elo) {
            float p = 0.f, q = 0.f;
#pragma unroll
            for (int j = 0; j < 8; j++) {
                p = fmaf(acc[i][j], alv[j], p);
                q = fmaf(acc[i][j], arv[j], q);
            }
            p += __shfl_down_sync(0xffffffffu, p, 1, 4);
            p += __shfl_down_sync(0xffffffffu, p, 2, 4);
            q += __shfl_down_sync(0xffffffffu, q, 1, 4);
            q += __shfl_down_sync(0xffffffffu, q, 2, 4);
            if ((tx & 3) == 0 && row < N_NODES) {
                elo[row * NH + hh] = p;
                ero[row * NH + hh] = q;
            }
        }
    }
}

// ---------------- fused GAT aggregation: warp per dst node ----------------
__global__ __launch_bounds__(256)
void gat_agg(int r, const float* __restrict__ el, const float* __restrict__ er,
             const float* __restrict__ fs, float* __restrict__ h2) {
    int d = (blockIdx.x * blockDim.x + threadIdx.x) >> 5;
    int lane = threadIdx.x & 31;
    if (d >= N_NODES) return;
    const int beg = g_rowptr[r][d];
    const int end = g_rowptr[r][d + 1];
    const float4 erd = *(const float4*)&er[d * NH];

    // phase 1: per-head sum of exp
    float s0 = 0.f, s1 = 0.f, s2 = 0.f, s3 = 0.f;
    for (int e = beg + lane; e < end; e += 32) {
        int s = g_colsrc[r][e];
        float4 elv = *(const float4*)&el[s * NH];
        float e0 = elv.x + erd.x; e0 = e0 > 0.f ? e0 : NEG_SLOPE * e0;
        float e1 = elv.y + erd.y; e1 = e1 > 0.f ? e1 : NEG_SLOPE * e1;
        float e2 = elv.z + erd.z; e2 = e2 > 0.f ? e2 : NEG_SLOPE * e2;
        float e3 = elv.w + erd.w; e3 = e3 > 0.f ? e3 : NEG_SLOPE * e3;
        s0 += expf(e0); s1 += expf(e1); s2 += expf(e2); s3 += expf(e3);
    }
#pragma unroll
    for (int off = 16; off >= 1; off >>= 1) {
        s0 += __shfl_xor_sync(0xffffffffu, s0, off);
        s1 += __shfl_xor_sync(0xffffffffu, s1, off);
        s2 += __shfl_xor_sync(0xffffffffu, s2, off);
        s3 += __shfl_xor_sync(0xffffffffu, s3, off);
    }

    // phase 2: weighted accumulate; lane covers fs cols lane*4..lane*4+3
    const int h = lane >> 3;
    const float er_h = (h == 0) ? erd.x : (h == 1) ? erd.y : (h == 2) ? erd.z : erd.w;
    const float s_h  = (h == 0) ? s0    : (h == 1) ? s1    : (h == 2) ? s2    : s3;
    const float inv_s = (end > beg) ? (1.f / s_h) : 0.f;
    const int co = lane * 4;

    float4 acc = make_float4(0.f, 0.f, 0.f, 0.f);
    int e = beg;
    for (; e + 2 <= end; e += 2) {           // unroll x2 for MLP
        int sA = g_colsrc[r][e];
        int sB = g_colsrc[r][e + 1];
        float4 ea = *(const float4*)&el[sA * NH];
        float4 eb = *(const float4*)&el[sB * NH];
        float4 fa = *(const float4*)&fs[(size_t)sA * NF + co];
        float4 fb = *(const float4*)&fs[(size_t)sB * NF + co];
        float elA = (h == 0) ? ea.x : (h == 1) ? ea.y : (h == 2) ? ea.z : ea.w;
        float elB = (h == 0) ? eb.x : (h == 1) ? eb.y : (h == 2) ? eb.z : eb.w;
        float vA = elA + er_h; vA = vA > 0.f ? vA : NEG_SLOPE * vA;
        float vB = elB + er_h; vB = vB > 0.f ? vB : NEG_SLOPE * vB;
        float aA = expf(vA) * inv_s;
        float aB = expf(vB) * inv_s;
        acc.x = fmaf(aA, fa.x, acc.x); acc.y = fmaf(aA, fa.y, acc.y);
        acc.z = fmaf(aA, fa.z, acc.z); acc.w = fmaf(aA, fa.w, acc.w);
        acc.x = fmaf(aB, fb.x, acc.x); acc.y = fmaf(aB, fb.y, acc.y);
        acc.z = fmaf(aB, fb.z, acc.z); acc.w = fmaf(aB, fb.w, acc.w);
    }
    if (e < end) {
        int s = g_colsrc[r][e];
        float4 ea = *(const float4*)&el[s * NH];
        float4 fa = *(const float4*)&fs[(size_t)s * NF + co];
        float elA = (h == 0) ? ea.x : (h == 1) ? ea.y : (h == 2) ? ea.z : ea.w;
        float vA = elA + er_h; vA = vA > 0.f ? vA : NEG_SLOPE * vA;
        float aA = expf(vA) * inv_s;
        acc.x = fmaf(aA, fa.x, acc.x); acc.y = fmaf(aA, fa.y, acc.y);
        acc.z = fmaf(aA, fa.z, acc.z); acc.w = fmaf(aA, fa.w, acc.w);
    }
    *(float4*)&h2[(size_t)d * NF + co] = acc;
}

// ---------------- layer finalize: t = h1 + relu(h2a+h2b+bias), + BN stats --
#define RPB 128
__global__ void finalize_stats(const float* __restrict__ h1,
                               const float* __restrict__ h2a,
                               const float* __restrict__ h2b,
                               const float* __restrict__ cb0,
                               const float* __restrict__ cb1,
                               float* __restrict__ t) {
    int col = threadIdx.x;
    float bias = cb0[col] + cb1[col];
    int r0 = blockIdx.x * RPB;
    double s = 0.0, s2 = 0.0;
    for (int r = 0; r < RPB; r++) {
        int row = r0 + r;
        if (row >= N_NODES) break;
        float v = h2a[(size_t)row * NF + col] + h2b[(size_t)row * NF + col] + bias;
        v = v > 0.f ? v : 0.f;
        v += h1[(size_t)row * NF + col];
        t[(size_t)row * NF + col] = v;
        s += v;
        s2 += (double)v * (double)v;
    }
    atomicAdd(&g_sum[col], s);
    atomicAdd(&g_sq[col], s2);
}

__global__ void stats128(const float* __restrict__ x) {
    int col = threadIdx.x;
    int r0 = blockIdx.x * RPB;
    double s = 0.0, s2 = 0.0;
    for (int r = 0; r < RPB; r++) {
        int row = r0 + r;
        if (row >= N_NODES) break;
        float v = x[(size_t)row * NF + col];
        s += v;
        s2 += (double)v * (double)v;
    }
    atomicAdd(&g_sum[col], s);
    atomicAdd(&g_sq[col], s2);
}

__global__ void normalize128(const float* __restrict__ x, const float* __restrict__ g,
                             const float* __restrict__ b, float* __restrict__ y,
                             int do_relu) {
    int col = threadIdx.x;
    double mu = g_sum[col] / (double)N_NODES;
    double var = g_sq[col] / (double)N_NODES - mu * mu;
    float sc = g[col] * rsqrtf((float)var + BN_EPS);
    float sh = b[col] - (float)mu * sc;
    int r0 = blockIdx.x * RPB;
    for (int r = 0; r < RPB; r++) {
        int row = r0 + r;
        if (row >= N_NODES) break;
        float v = x[(size_t)row * NF + col] * sc + sh;
        if (do_relu) v = v > 0.f ? v : 0.f;
        y[(size_t)row * NF + col] = v;
    }
}

// ---------------- final 128 -> 16 GEMM ----------------
__global__ __launch_bounds__(128)
void gemm_out(const float* __restrict__ x, const float* __restrict__ W2,
              const float* __restrict__ b2, float* __restrict__ out) {
    __shared__ float xs[8][NF];
    int tid = threadIdx.x;
    int r0 = blockIdx.x * 8;
#pragma unroll
    for (int i = 0; i < 8; i++) {
        int row = r0 + i;
        xs[i][tid] = (row < N_NODES) ? x[(size_t)row * NF + tid] : 0.f;
    }
    __syncthreads();
    int row = tid >> 4;
    int c = tid & 15;
    float acc = b2[c];
#pragma unroll 8
    for (int k = 0; k < NF; k++) acc = fmaf(xs[row][k], W2[k * 16 + c], acc);
    if (r0 + row < N_NODES) out[(size_t)(r0 + row) * 16 + c] = acc;
}

// ---------------- host ----------------
extern "C" void kernel_launch(void* const* d_in, const int* in_sizes, int n_in,
                              void* d_out, int out_size) {
    const float* feat     = (const float*)d_in[0];
    const float* fc_W     = (const float*)d_in[1];
    const float* attn_l   = (const float*)d_in[2];
    const float* attn_r   = (const float*)d_in[3];
    const float* conv_b   = (const float*)d_in[4];
    const float* skip_W   = (const float*)d_in[5];
    const float* skip_b   = (const float*)d_in[6];
    const float* norm_g   = (const float*)d_in[7];
    const float* norm_b   = (const float*)d_in[8];
    const float* clf_W1   = (const float*)d_in[9];
    const float* clf_b1   = (const float*)d_in[10];
    const float* clf_g    = (const float*)d_in[11];
    const float* clf_b    = (const float*)d_in[12];
    const float* clf_W2   = (const float*)d_in[13];
    const float* clf_b2   = (const float*)d_in[14];
    const int*   src      = (const int*)d_in[15];
    const int*   dst      = (const int*)d_in[16];
    float* out = (float*)d_out;

    float *h, *h1, *fs, *h2a, *h2b, *el, *er;
    cudaGetSymbolAddress((void**)&h,   g_h);
    cudaGetSymbolAddress((void**)&h1,  g_h1);
    cudaGetSymbolAddress((void**)&fs,  g_fs);
    cudaGetSymbolAddress((void**)&h2a, g_h2a);
    cudaGetSymbolAddress((void**)&h2b, g_h2b);
    cudaGetSymbolAddress((void**)&el,  g_el);
    cudaGetSymbolAddress((void**)&er,  g_er);

    const int gemm_grid = (N_NODES + 127) / 128;
    const int node_grid = (N_NODES + 255) / 256;
    const int edge_grid = (N_EDGES + 255) / 256;
    const int agg_grid  = (N_NODES * 32 + 255) / 256;
    const int bn_grid   = (N_NODES + RPB - 1) / RPB;

    // ---- CSR build (once, reused by both layers) ----
    for (int r = 0; r < 2; r++) {
        const int* dr = dst + (size_t)r * N_EDGES;
        const int* sr = src + (size_t)r * N_EDGES;
        zero_deg<<<node_grid, 256>>>(r);
        hist_deg<<<edge_grid, 256>>>(dr, r);
        scan_blocks<<<N_SCANB, SCAN_B>>>(r);
        scan_bsum<<<1, 64>>>(r);
        scan_finish<<<node_grid, 256>>>(r);
        scatter_csr<<<edge_grid, 256>>>(sr, dr, r);
    }

    const float* hin = feat;
    for (int l = 0; l < 2; l++) {
        gemm128<<<gemm_grid, 256>>>(hin, skip_W + l * NF * NF, skip_b + l * NF,
                                    h1, nullptr, nullptr, nullptr, nullptr);
        for (int r = 0; r < 2; r++) {
            int lr = l * 2 + r;
            gemm128<<<gemm_grid, 256>>>(hin, fc_W + (size_t)lr * NF * NF, nullptr,
                                        fs, attn_l + lr * NF, attn_r + lr * NF, el, er);
            gat_agg<<<agg_grid, 256>>>(r, el, er, fs, r == 0 ? h2a : h2b);
        }
        zero_stats<<<1, 128>>>();
        finalize_stats<<<bn_grid, 128>>>(h1, h2a, h2b,
                                         conv_b + (l * 2 + 0) * NF,
                                         conv_b + (l * 2 + 1) * NF, fs);
        normalize128<<<bn_grid, 128>>>(fs, norm_g + l * NF, norm_b + l * NF, h, 0);
        hin = h;
    }

    // classifier
    gemm128<<<gemm_grid, 256>>>(h, clf_W1, clf_b1, h1, nullptr, nullptr, nullptr, nullptr);
    zero_stats<<<1, 128>>>();
    stats128<<<bn_grid, 128>>>(h1);
    normalize128<<<bn_grid, 128>>>(h1, clf_g, clf_b, fs, 1);
    gemm_out<<<(N_NODES + 7) / 8, 128>>>(fs, clf_W2, clf_b2, out);
}

// round 6
// speedup vs baseline: 1.3556x; 1.1172x over previous
#include <cuda_runtime.h>
#include <math.h>

#define N_NODES 50000
#define N_EDGES 500000
#define NF      128
#define NH      4
#define NEG_SLOPE 0.2f
#define BN_EPS 1e-5f
#define SCAN_B  1024
#define N_SCANB ((N_NODES + SCAN_B - 1) / SCAN_B)   // 49

// ---------------- scratch (device globals; no allocation allowed) ----------
__device__ float g_h  [N_NODES * NF];
__device__ float g_h1 [N_NODES * NF];
__device__ float g_fsa[N_NODES * NF];
__device__ float g_fsb[N_NODES * NF];
__device__ float g_h2 [N_NODES * NF];
__device__ float g_ela[N_NODES * NH];
__device__ float g_era[N_NODES * NH];
__device__ float g_elb[N_NODES * NH];
__device__ float g_erb[N_NODES * NH];
__device__ double g_sum[3][NF];
__device__ double g_sq [3][NF];
// CSR (2 relations)
__device__ int g_deg   [2][N_NODES];
__device__ int g_rowptr[2][N_NODES + 1];
__device__ int g_cursor[2][N_NODES];
__device__ int g_colsrc[2][N_EDGES];
__device__ int g_bsum  [2][N_SCANB];

// ---------------- small utility kernels ----------------
__global__ void zero_stats_all() {        // 3 slots x 128
    int s = threadIdx.x >> 7;
    int c = threadIdx.x & 127;
    if (threadIdx.x < 384) { g_sum[s][c] = 0.0; g_sq[s][c] = 0.0; }
}

// ---------------- CSR build (both relations in one grid) ----------------
__global__ void zero_deg_all() {
    int i = blockIdx.x * blockDim.x + threadIdx.x;
    if (i < 2 * N_NODES) ((int*)g_deg)[i] = 0;
}

__global__ void hist_deg_all(const int* __restrict__ dst) {   // dst = [2][E]
    int i = blockIdx.x * blockDim.x + threadIdx.x;
    if (i >= 2 * N_EDGES) return;
    int r = i / N_EDGES;
    atomicAdd(&g_deg[r][dst[i]], 1);
}

__global__ __launch_bounds__(SCAN_B)
void scan_blocks_all() {
    __shared__ int tmp[SCAN_B];
    int r  = blockIdx.x / N_SCANB;
    int bb = blockIdx.x % N_SCANB;
    int i = bb * SCAN_B + threadIdx.x;
    int v = (i < N_NODES) ? g_deg[r][i] : 0;
    tmp[threadIdx.x] = v;
    __syncthreads();
    for (int off = 1; off < SCAN_B; off <<= 1) {
        int t = (threadIdx.x >= off) ? tmp[threadIdx.x - off] : 0;
        __syncthreads();
        tmp[threadIdx.x] += t;
        __syncthreads();
    }
    if (i < N_NODES) g_rowptr[r][i] = tmp[threadIdx.x] - v;   // exclusive
    if (threadIdx.x == SCAN_B - 1) g_bsum[r][bb] = tmp[SCAN_B - 1];
}

__global__ void scan_bsum_all() {     // 2 blocks, one per relation
    __shared__ int s[64];
    int r = blockIdx.x;
    int v = (threadIdx.x < N_SCANB) ? g_bsum[r][threadIdx.x] : 0;
    s[threadIdx.x] = v;
    __syncthreads();
    for (int off = 1; off < 64; off <<= 1) {
        int t = (threadIdx.x >= off) ? s[threadIdx.x - off] : 0;
        __syncthreads();
        s[threadIdx.x] += t;
        __syncthreads();
    }
    if (threadIdx.x < N_SCANB) g_bsum[r][threadIdx.x] = s[threadIdx.x] - v;  // exclusive
}

__global__ void scan_finish_all() {
    int i = blockIdx.x * blockDim.x + threadIdx.x;
    if (i >= 2 * N_NODES) return;
    int r = i / N_NODES;
    int n = i % N_NODES;
    int v = g_rowptr[r][n] + g_bsum[r][n / SCAN_B];
    g_rowptr[r][n] = v;
    g_cursor[r][n] = v;
    if (n == 0) g_rowptr[r][N_NODES] = N_EDGES;
}

__global__ void scatter_csr_all(const int* __restrict__ src, const int* __restrict__ dst) {
    int i = blockIdx.x * blockDim.x + threadIdx.x;
    if (i >= 2 * N_EDGES) return;
    int r = i / N_EDGES;
    int p = atomicAdd(&g_cursor[r][dst[i]], 1);
    g_colsrc[r][p] = src[i];
}

// ---------------- software-pipelined SGEMM (+ optional attn epilogue) ------
__device__ __forceinline__ void cp_async16(void* smem, const void* gmem) {
    unsigned sa = (unsigned)__cvta_generic_to_shared(smem);
    asm volatile("cp.async.cg.shared.global [%0], [%1], 16;\n"
                 :: "r"(sa), "l"(gmem));
}
__device__ __forceinline__ void cp_commit() {
    asm volatile("cp.async.commit_group;\n");
}
__device__ __forceinline__ void cp_wait0() {
    asm volatile("cp.async.wait_group 0;\n" ::: "memory");
}

__global__ __launch_bounds__(256, 2)
void gemm128(const float* __restrict__ A, const float* __restrict__ W,
             const float* __restrict__ bias, float* __restrict__ C,
             const float* __restrict__ al, const float* __restrict__ ar,
             float* __restrict__ elo, float* __restrict__ ero) {
    __shared__ float As[2][8][128];
    __shared__ float Ws[2][8][128];

    const int tid = threadIdx.x;
    const int tx = tid & 15;
    const int ty = tid >> 4;
    const int rb = blockIdx.x * 128;

    const int arow = tid >> 1;
    const int acol = (tid & 1) * 4;
    const int wrow = tid >> 5;
    const int wcol = (tid & 31) * 4;
    const int gr = rb + arow;
    const bool arow_ok = (gr < N_NODES);

    float acc[8][8];
#pragma unroll
    for (int i = 0; i < 8; i++)
#pragma unroll
        for (int j = 0; j < 8; j++) acc[i][j] = 0.f;

    float4 av = make_float4(0.f, 0.f, 0.f, 0.f);
    if (arow_ok) av = *(const float4*)&A[(size_t)gr * NF + acol];
    cp_async16(&Ws[0][wrow][wcol], &W[(size_t)wrow * NF + wcol]);
    cp_commit();
    As[0][acol + 0][arow] = av.x;
    As[0][acol + 1][arow] = av.y;
    As[0][acol + 2][arow] = av.z;
    As[0][acol + 3][arow] = av.w;
    cp_wait0();
    __syncthreads();

    int buf = 0;
    for (int t = 0; t < 16; t++) {
        const int kc = t * 8;
        const bool has_next = (t + 1 < 16);
        float4 avn;
        if (has_next) {
            avn = make_float4(0.f, 0.f, 0.f, 0.f);
            if (arow_ok) avn = *(const float4*)&A[(size_t)gr * NF + kc + 8 + acol];
            cp_async16(&Ws[buf ^ 1][wrow][wcol], &W[(size_t)(kc + 8 + wrow) * NF + wcol]);
            cp_commit();
        }

#pragma unroll
        for (int kk = 0; kk < 8; kk++) {
            float a[8], b[8];
            *(float4*)&a[0] = *(float4*)&As[buf][kk][ty * 8];
            *(float4*)&a[4] = *(float4*)&As[buf][kk][ty * 8 + 4];
            *(float4*)&b[0] = *(float4*)&Ws[buf][kk][tx * 8];
            *(float4*)&b[4] = *(float4*)&Ws[buf][kk][tx * 8 + 4];
#pragma unroll
            for (int i = 0; i < 8; i++)
#pragma unroll
                for (int j = 0; j < 8; j++)
                    acc[i][j] = fmaf(a[i], b[j], acc[i][j]);
        }

        if (has_next) {
            As[buf ^ 1][acol + 0][arow] = avn.x;
            As[buf ^ 1][acol + 1][arow] = avn.y;
            As[buf ^ 1][acol + 2][arow] = avn.z;
            As[buf ^ 1][acol + 3][arow] = avn.w;
            cp_wait0();
        }
        __syncthreads();
        buf ^= 1;
    }

    const int cb = tx * 8;
    float bcol[8];
#pragma unroll
    for (int j = 0; j < 8; j++) bcol[j] = bias ? bias[cb + j] : 0.f;
    float alv[8], arv[8];
    if (elo) {
#pragma unroll
        for (int j = 0; j < 8; j++) { alv[j] = al[cb + j]; arv[j] = ar[cb + j]; }
    }
    const int hh = tx >> 2;

#pragma unroll
    for (int i = 0; i < 8; i++) {
        int row = rb + ty * 8 + i;
        if (row < N_NODES) {
            float4 o0 = make_float4(acc[i][0] + bcol[0], acc[i][1] + bcol[1],
                                    acc[i][2] + bcol[2], acc[i][3] + bcol[3]);
            float4 o1 = make_float4(acc[i][4] + bcol[4], acc[i][5] + bcol[5],
                                    acc[i][6] + bcol[6], acc[i][7] + bcol[7]);
            *(float4*)&C[(size_t)row * NF + cb]     = o0;
            *(float4*)&C[(size_t)row * NF + cb + 4] = o1;
        }
        if (elo) {
            float p = 0.f, q = 0.f;
#pragma unroll
            for (int j = 0; j < 8; j++) {
                p = fmaf(acc[i][j], alv[j], p);
                q = fmaf(acc[i][j], arv[j], q);
            }
            p += __shfl_down_sync(0xffffffffu, p, 1, 4);
            p += __shfl_down_sync(0xffffffffu, p, 2, 4);
            q += __shfl_down_sync(0xffffffffu, q, 1, 4);
            q += __shfl_down_sync(0xffffffffu, q, 2, 4);
            if ((tx & 3) == 0 && row < N_NODES) {
                elo[row * NH + hh] = p;
                ero[row * NH + hh] = q;
            }
        }
    }
}

// ---------------- fused dual-relation single-pass GAT aggregation ----------
// warp per dst node; lane covers cols lane*4.., head = lane>>3.
// Single pass: acc = sum w*f, s = sum w; out = acc/s. Both relations summed.
__device__ __forceinline__ float agg_one_rel(
    int r, int d, int lane, int h, int co,
    const float* __restrict__ el, const float* __restrict__ er,
    const float* __restrict__ fs, float4* acc_out) {
    const int beg = g_rowptr[r][d];
    const int end = g_rowptr[r][d + 1];
    const float er_h = er[d * NH + h];
    float4 acc = make_float4(0.f, 0.f, 0.f, 0.f);
    float sh = 0.f;
    int e = beg;
    for (; e + 2 <= end; e += 2) {
        int sA = g_colsrc[r][e];
        int sB = g_colsrc[r][e + 1];
        float elA = el[sA * NH + h];
        float elB = el[sB * NH + h];
        float4 fa = *(const float4*)&fs[(size_t)sA * NF + co];
        float4 fb = *(const float4*)&fs[(size_t)sB * NF + co];
        float vA = elA + er_h; vA = vA > 0.f ? vA : NEG_SLOPE * vA;
        float vB = elB + er_h; vB = vB > 0.f ? vB : NEG_SLOPE * vB;
        float wA = expf(vA);
        float wB = expf(vB);
        sh += wA + wB;
        acc.x = fmaf(wA, fa.x, acc.x); acc.y = fmaf(wA, fa.y, acc.y);
        acc.z = fmaf(wA, fa.z, acc.z); acc.w = fmaf(wA, fa.w, acc.w);
        acc.x = fmaf(wB, fb.x, acc.x); acc.y = fmaf(wB, fb.y, acc.y);
        acc.z = fmaf(wB, fb.z, acc.z); acc.w = fmaf(wB, fb.w, acc.w);
    }
    if (e < end) {
        int s = g_colsrc[r][e];
        float elA = el[s * NH + h];
        float4 fa = *(const float4*)&fs[(size_t)s * NF + co];
        float vA = elA + er_h; vA = vA > 0.f ? vA : NEG_SLOPE * vA;
        float wA = expf(vA);
        sh += wA;
        acc.x = fmaf(wA, fa.x, acc.x); acc.y = fmaf(wA, fa.y, acc.y);
        acc.z = fmaf(wA, fa.z, acc.z); acc.w = fmaf(wA, fa.w, acc.w);
    }
    *acc_out = acc;
    return (end > beg) ? (1.f / sh) : 0.f;
}

__global__ __launch_bounds__(256)
void gat_agg2(const float* __restrict__ ela, const float* __restrict__ era,
              const float* __restrict__ fsa,
              const float* __restrict__ elb, const float* __restrict__ erb,
              const float* __restrict__ fsb,
              float* __restrict__ h2) {
    int d = (blockIdx.x * blockDim.x + threadIdx.x) >> 5;
    int lane = threadIdx.x & 31;
    if (d >= N_NODES) return;
    const int h = lane >> 3;
    const int co = lane * 4;

    float4 a0, a1;
    float i0 = agg_one_rel(0, d, lane, h, co, ela, era, fsa, &a0);
    float i1 = agg_one_rel(1, d, lane, h, co, elb, erb, fsb, &a1);

    float4 o;
    o.x = fmaf(a0.x, i0, a1.x * i1);
    o.y = fmaf(a0.y, i0, a1.y * i1);
    o.z = fmaf(a0.z, i0, a1.z * i1);
    o.w = fmaf(a0.w, i0, a1.w * i1);
    *(float4*)&h2[(size_t)d * NF + co] = o;
}

// ---------------- layer finalize: t = h1 + relu(h2 + bias), + BN stats -----
#define RPB 128
__global__ void finalize_stats(const float* __restrict__ h1,
                               const float* __restrict__ h2,
                               const float* __restrict__ cb0,
                               const float* __restrict__ cb1,
                               float* __restrict__ t, int slot) {
    int col = threadIdx.x;
    float bias = cb0[col] + cb1[col];
    int r0 = blockIdx.x * RPB;
    double s = 0.0, s2 = 0.0;
    for (int r = 0; r < RPB; r++) {
        int row = r0 + r;
        if (row >= N_NODES) break;
        float v = h2[(size_t)row * NF + col] + bias;
        v = v > 0.f ? v : 0.f;
        v += h1[(size_t)row * NF + col];
        t[(size_t)row * NF + col] = v;
        s += v;
        s2 += (double)v * (double)v;
    }
    atomicAdd(&g_sum[slot][col], s);
    atomicAdd(&g_sq[slot][col], s2);
}

__global__ void stats128(const float* __restrict__ x, int slot) {
    int col = threadIdx.x;
    int r0 = blockIdx.x * RPB;
    double s = 0.0, s2 = 0.0;
    for (int r = 0; r < RPB; r++) {
        int row = r0 + r;
        if (row >= N_NODES) break;
        float v = x[(size_t)row * NF + col];
        s += v;
        s2 += (double)v * (double)v;
    }
    atomicAdd(&g_sum[slot][col], s);
    atomicAdd(&g_sq[slot][col], s2);
}

__global__ void normalize128(const float* __restrict__ x, const float* __restrict__ g,
                             const float* __restrict__ b, float* __restrict__ y,
                             int do_relu, int slot) {
    int col = threadIdx.x;
    double mu = g_sum[slot][col] / (double)N_NODES;
    double var = g_sq[slot][col] / (double)N_NODES - mu * mu;
    float sc = g[col] * rsqrtf((float)var + BN_EPS);
    float sh = b[col] - (float)mu * sc;
    int r0 = blockIdx.x * RPB;
    for (int r = 0; r < RPB; r++) {
        int row = r0 + r;
        if (row >= N_NODES) break;
        float v = x[(size_t)row * NF + col] * sc + sh;
        if (do_relu) v = v > 0.f ? v : 0.f;
        y[(size_t)row * NF + col] = v;
    }
}

// ---------------- final 128 -> 16 GEMM ----------------
__global__ __launch_bounds__(128)
void gemm_out(const float* __restrict__ x, const float* __restrict__ W2,
              const float* __restrict__ b2, float* __restrict__ out) {
    __shared__ float xs[8][NF];
    int tid = threadIdx.x;
    int r0 = blockIdx.x * 8;
#pragma unroll
    for (int i = 0; i < 8; i++) {
        int row = r0 + i;
        xs[i][tid] = (row < N_NODES) ? x[(size_t)row * NF + tid] : 0.f;
    }
    __syncthreads();
    int row = tid >> 4;
    int c = tid & 15;
    float acc = b2[c];
#pragma unroll 8
    for (int k = 0; k < NF; k++) acc = fmaf(xs[row][k], W2[k * 16 + c], acc);
    if (r0 + row < N_NODES) out[(size_t)(r0 + row) * 16 + c] = acc;
}

// ---------------- host ----------------
extern "C" void kernel_launch(void* const* d_in, const int* in_sizes, int n_in,
                              void* d_out, int out_size) {
    const float* feat     = (const float*)d_in[0];
    const float* fc_W     = (const float*)d_in[1];
    const float* attn_l   = (const float*)d_in[2];
    const float* attn_r   = (const float*)d_in[3];
    const float* conv_b   = (const float*)d_in[4];
    const float* skip_W   = (const float*)d_in[5];
    const float* skip_b   = (const float*)d_in[6];
    const float* norm_g   = (const float*)d_in[7];
    const float* norm_b   = (const float*)d_in[8];
    const float* clf_W1   = (const float*)d_in[9];
    const float* clf_b1   = (const float*)d_in[10];
    const float* clf_g    = (const float*)d_in[11];
    const float* clf_b    = (const float*)d_in[12];
    const float* clf_W2   = (const float*)d_in[13];
    const float* clf_b2   = (const float*)d_in[14];
    const int*   src      = (const int*)d_in[15];
    const int*   dst      = (const int*)d_in[16];
    float* out = (float*)d_out;

    float *h, *h1, *fsa, *fsb, *h2, *ela, *era, *elb, *erb;
    cudaGetSymbolAddress((void**)&h,   g_h);
    cudaGetSymbolAddress((void**)&h1,  g_h1);
    cudaGetSymbolAddress((void**)&fsa, g_fsa);
    cudaGetSymbolAddress((void**)&fsb, g_fsb);
    cudaGetSymbolAddress((void**)&h2,  g_h2);
    cudaGetSymbolAddress((void**)&ela, g_ela);
    cudaGetSymbolAddress((void**)&era, g_era);
    cudaGetSymbolAddress((void**)&elb, g_elb);
    cudaGetSymbolAddress((void**)&erb, g_erb);

    const int gemm_grid  = (N_NODES + 127) / 128;
    const int node2_grid = (2 * N_NODES + 255) / 256;
    const int edge2_grid = (2 * N_EDGES + 255) / 256;
    const int agg_grid   = (N_NODES * 32 + 255) / 256;
    const int bn_grid    = (N_NODES + RPB - 1) / RPB;

    // ---- CSR build (both relations per launch) + stats zero ----
    zero_stats_all<<<1, 384>>>();
    zero_deg_all<<<node2_grid, 256>>>();
    hist_deg_all<<<edge2_grid, 256>>>(dst);
    scan_blocks_all<<<2 * N_SCANB, SCAN_B>>>();
    scan_bsum_all<<<2, 64>>>();
    scan_finish_all<<<node2_grid, 256>>>();
    scatter_csr_all<<<edge2_grid, 256>>>(src, dst);

    const float* hin = feat;
    for (int l = 0; l < 2; l++) {
        gemm128<<<gemm_grid, 256>>>(hin, skip_W + l * NF * NF, skip_b + l * NF,
                                    h1, nullptr, nullptr, nullptr, nullptr);
        int lr0 = l * 2, lr1 = l * 2 + 1;
        gemm128<<<gemm_grid, 256>>>(hin, fc_W + (size_t)lr0 * NF * NF, nullptr,
                                    fsa, attn_l + lr0 * NF, attn_r + lr0 * NF, ela, era);
        gemm128<<<gemm_grid, 256>>>(hin, fc_W + (size_t)lr1 * NF * NF, nullptr,
                                    fsb, attn_l + lr1 * NF, attn_r + lr1 * NF, elb, erb);
        gat_agg2<<<agg_grid, 256>>>(ela, era, fsa, elb, erb, fsb, h2);
        finalize_stats<<<bn_grid, 128>>>(h1, h2,
                                         conv_b + lr0 * NF, conv_b + lr1 * NF,
                                         fsa, l);
        normalize128<<<bn_grid, 128>>>(fsa, norm_g + l * NF, norm_b + l * NF, h, 0, l);
        hin = h;
    }

    // classifier
    gemm128<<<gemm_grid, 256>>>(h, clf_W1, clf_b1, h1, nullptr, nullptr, nullptr, nullptr);
    stats128<<<bn_grid, 128>>>(h1, 2);
    normalize128<<<bn_grid, 128>>>(h1, clf_g, clf_b, fsa, 1, 2);
    gemm_out<<<(N_NODES + 7) / 8, 128>>>(fsa, clf_W2, clf_b2, out);
}